// round 12
// baseline (speedup 1.0000x reference)
#include <cuda_runtime.h>
#include <math.h>

#define TPB 64
#define NPART 2048

__device__ float g_partials[NPART];
__device__ unsigned int g_count;

// One Sutherland-Hodgman clip pass -- FULLY BRANCH-FREE.
// Polygon lives in a thread-private smem column of float2 ([slot][tid],
// stride TPB -> conflict-free 64-bit accesses). Slot 9 is a per-thread
// trash slot: every push is an unconditional STS whose 32-bit offset is
// selected between the write cursor and trash, so no BSSY/BSYNC divergence.
// Wraparound handled by an appended copy of vertex 0 at slot np.
// In-place safe: all INCAP+1 slots are read before any write.
// Reads of slots >= np are predicate-discarded; garbage there is harmless.
// Reference semantics: keep = (val <= 0), crossing = strict sign change,
// frozen = empty result -> keep pre-clip polygon, stop clipping.
template <int INCAP>
__device__ __forceinline__ void clip_edge_smem(float a, float b, float c,
                                               float2* __restrict__ sp,
                                               int t, int& np, bool& frozen) {
    bool doPass = !frozen && (np > 2);

    float2 r[INCAP + 1];
    float v[INCAP + 1];
#pragma unroll
    for (int j = 0; j <= INCAP; j++) {
        r[j] = sp[j * TPB + t];
        v[j] = a * r[j].x + b * r[j].y + c;
    }

    const int TRASH = 9 * TPB + t;   // per-thread trash slot offset
    int wo = t;                      // write cursor offset (32-bit)
    int nn = 0;
#pragma unroll
    for (int j = 0; j < INCAP; j++) {
        bool act  = doPass && (j < np);
        bool keep = act && (v[j] <= 0.0f);
        bool crs  = act && (v[j] * v[j + 1] < 0.0f);

        // keep push (unconditional store, selected 32-bit offset)
        sp[keep ? wo : TRASH] = r[j];
        wo += keep ? TPB : 0;
        nn += keep ? 1 : 0;

        // intersection (computed unconditionally; trash absorbs garbage)
        float tx = r[j + 1].x, ty = r[j + 1].y;
        float a2 = ty - r[j].y;
        float b2 = r[j].x - tx;
        float c2 = tx * r[j].y - ty * r[j].x;
        float wd = a * b2 - b * a2;
        float iw = __fdividef(1.0f, wd);
        float2 ip;
        ip.x = (b * c2 - c * b2) * iw;
        ip.y = (c * a2 - a * c2) * iw;
        sp[crs ? wo : TRASH] = ip;
        wo += crs ? TPB : 0;
        nn += crs ? 1 : 0;
    }

    // append new vertex 0 at slot nn (branch-free), update state by selects
    bool ok = doPass && (nn > 0);
    float2 f0 = sp[t];               // new slot 0 (if any push happened)
    sp[ok ? wo : TRASH] = f0;        // wo == nn*TPB + t
    np = ok ? nn : np;               // geometric bound: nn <= INCAP+1 <= 8
    frozen = frozen || (doPass && nn == 0);
}

__global__ void __launch_bounds__(TPB, 16)
giou_kernel(const float* __restrict__ pred,
            const float* __restrict__ tgt,
            float* __restrict__ out, int n) {
    __shared__ float2 s_xy[10 * TPB];  // clip polygon (+append, +trash slot)
    __shared__ float2 c_xy[8 * TPB];   // 8 corners (0-3 pred, 4-7 tgt)

    int t = threadIdx.x;
    int i = blockIdx.x * TPB + t;
    float giou = 0.0f;

    if (i < n) {
        const float2* pb = (const float2*)(pred + 6 * i);
        const float2* tb = (const float2*)(tgt + 6 * i);
        float2 p0 = __ldg(pb), p1 = __ldg(pb + 1), p2 = __ldg(pb + 2);
        float2 t0 = __ldg(tb), t1 = __ldg(tb + 1), t2 = __ldg(tb + 2);
        float area_sum = p1.x * p1.y + t1.x * t1.y;  // pa + ta

        // ---- corners into smem (float2); pred corners seed polygon + append ----
        {
            float rinv = rsqrtf(fmaf(p2.x, p2.x, p2.y * p2.y));
            float cth = p2.y * rinv, sth = p2.x * rinv;
            float hw = 0.5f * p1.x, hl = 0.5f * p1.y;
            float2 c0 = make_float2(p0.x - hw * cth - hl * sth, p0.y - hw * sth + hl * cth);
            float2 c1 = make_float2(p0.x - hw * cth + hl * sth, p0.y - hw * sth - hl * cth);
            float2 c2 = make_float2(p0.x + hw * cth + hl * sth, p0.y + hw * sth - hl * cth);
            float2 c3 = make_float2(p0.x + hw * cth - hl * sth, p0.y + hw * sth + hl * cth);
            c_xy[0 * TPB + t] = c0;  s_xy[0 * TPB + t] = c0;
            c_xy[1 * TPB + t] = c1;  s_xy[1 * TPB + t] = c1;
            c_xy[2 * TPB + t] = c2;  s_xy[2 * TPB + t] = c2;
            c_xy[3 * TPB + t] = c3;  s_xy[3 * TPB + t] = c3;
            s_xy[4 * TPB + t] = c0;  // append: wraparound copy of vertex 0
        }
        {
            float rinv = rsqrtf(fmaf(t2.x, t2.x, t2.y * t2.y));
            float cth = t2.y * rinv, sth = t2.x * rinv;
            float hw = 0.5f * t1.x, hl = 0.5f * t1.y;
            c_xy[4 * TPB + t] = make_float2(t0.x - hw * cth - hl * sth, t0.y - hw * sth + hl * cth);
            c_xy[5 * TPB + t] = make_float2(t0.x - hw * cth + hl * sth, t0.y - hw * sth - hl * cth);
            c_xy[6 * TPB + t] = make_float2(t0.x + hw * cth + hl * sth, t0.y + hw * sth - hl * cth);
            c_xy[7 * TPB + t] = make_float2(t0.x + hw * cth - hl * sth, t0.y + hw * sth + hl * cth);
        }

        // ---- clip by the 4 target half-planes (planes built JIT from smem) ----
        int np = 4;
        bool frozen = false;
#pragma unroll
        for (int e = 0; e < 4; e++) {
            const int e1 = (e + 1) & 3;
            float2 P = c_xy[(4 + e) * TPB + t];
            float2 Q = c_xy[(4 + e1) * TPB + t];
            float a = Q.y - P.y;
            float b = P.x - Q.x;
            float c = Q.x * P.y - Q.y * P.x;
            if (e == 0)      clip_edge_smem<4>(a, b, c, s_xy, t, np, frozen);
            else if (e == 1) clip_edge_smem<5>(a, b, c, s_xy, t, np, frozen);
            else if (e == 2) clip_edge_smem<6>(a, b, c, s_xy, t, np, frozen);
            else             clip_edge_smem<7>(a, b, c, s_xy, t, np, frozen);
        }

        // ---- shoelace over final polygon (append makes next = j+1) ----
        float s2 = 0.0f;
        {
            float2 q[9];
#pragma unroll
            for (int k = 0; k < 9; k++) q[k] = s_xy[k * TPB + t];
#pragma unroll
            for (int j = 0; j < 8; j++) {
                bool act = (j < np);
                float tm = q[j].x * q[j + 1].y - q[j].y * q[j + 1].x;
                s2 += act ? tm : 0.0f;
            }
        }
        float inter = (np > 2) ? 0.5f * fabsf(s2) : 0.0f;

        float uni = area_sum - inter;
        float iou = inter * __fdividef(1.0f, uni + 1e-16f);
        out[i] = iou;

        // ---- convex hull area (reference all-pairs form) ----
        // Corners in registers (clip pressure over). Antisymmetry: each
        // unordered pair once, both directed validities via min/max trees.
        float2 P[8];
#pragma unroll
        for (int k = 0; k < 8; k++) P[k] = c_xy[k * TPB + t];

        float hs = 0.0f;
#pragma unroll
        for (int ii = 0; ii < 8; ii++) {
            float dx[8], dy[8];
#pragma unroll
            for (int k = 0; k < 8; k++) {
                dx[k] = P[k].x - P[ii].x;
                dy[k] = P[k].y - P[ii].y;
            }
#pragma unroll
            for (int jj = ii + 1; jj < 8; jj++) {
                float ex = dx[jj], ey = dy[jj];
                float cr[6];
                int c6 = 0;
#pragma unroll
                for (int k = 0; k < 8; k++) {
                    if (k == ii || k == jj) continue;  // cross == 0 there
                    cr[c6++] = ex * dy[k] - ey * dx[k];
                }
                float mn = fminf(fminf(fminf(cr[0], cr[1]), fminf(cr[2], cr[3])),
                                 fminf(cr[4], cr[5]));
                float mx = fmaxf(fmaxf(fmaxf(cr[0], cr[1]), fmaxf(cr[2], cr[3])),
                                 fmaxf(cr[4], cr[5]));
                float len2 = ex * ex + ey * ey;
                bool okL = (len2 > 1e-12f) && (mn >= -1e-6f);  // ii -> jj
                bool okR = (len2 > 1e-12f) && (mx <= 1e-6f);   // jj -> ii
                float cij = P[ii].x * ey - P[ii].y * ex;  // == xi*yj - yi*xj
                hs += okL ? cij : 0.0f;
                hs += okR ? -cij : 0.0f;
            }
        }
        float hull = 0.5f * fabsf(hs);

        giou = 1.0f - (iou - (hull - uni) * __fdividef(1.0f, hull + 1e-16f));
    }

    // ---- deterministic in-kernel reduction ----
#pragma unroll
    for (int off = 16; off > 0; off >>= 1)
        giou += __shfl_down_sync(0xffffffffu, giou, off);

    __shared__ float wsum[TPB / 32];
    __shared__ bool isLast;
    if ((t & 31) == 0) wsum[t >> 5] = giou;
    __syncthreads();

    if (t == 0) {
        float bs = 0.0f;
#pragma unroll
        for (int w = 0; w < TPB / 32; w++) bs += wsum[w];
        g_partials[blockIdx.x] = bs;
        __threadfence();
        unsigned c = atomicAdd(&g_count, 1u);
        isLast = (c == gridDim.x - 1);
    }
    __syncthreads();

    if (isLast) {
        __threadfence();
        float v = 0.0f;
        for (int j = t; j < (int)gridDim.x; j += TPB)
            v += ((volatile float*)g_partials)[j];
#pragma unroll
        for (int off = 16; off > 0; off >>= 1)
            v += __shfl_down_sync(0xffffffffu, v, off);
        if ((t & 31) == 0) wsum[t >> 5] = v;
        __syncthreads();
        if (t == 0) {
            float tot = 0.0f;
#pragma unroll
            for (int w = 0; w < TPB / 32; w++) tot += wsum[w];
            out[n] = tot;
            g_count = 0;  // reset for next graph replay
        }
    }
}

extern "C" void kernel_launch(void* const* d_in, const int* in_sizes, int n_in,
                              void* d_out, int out_size) {
    const float* pred = (const float*)d_in[0];
    const float* tgt  = (const float*)d_in[1];
    float* out = (float*)d_out;
    int n = in_sizes[0] / 6;
    int nblocks = (n + TPB - 1) / TPB;
    giou_kernel<<<nblocks, TPB>>>(pred, tgt, out, n);
}

// round 14
// speedup vs baseline: 1.0209x; 1.0209x over previous
#include <cuda_runtime.h>
#include <math.h>

#define TPB 128
#define NPART 2048

__device__ float g_partials[NPART];
__device__ unsigned int g_count;

// First Sutherland-Hodgman clip pass, input polygon (pred quad) in REGISTERS.
// The caller MUST have pre-seeded smem slots 0..4 with the quad (+wrap copy):
// if this pass produces an empty polygon (frozen), the seed remains in smem
// and the shoelace computes the pre-clip area (reference "frozen" semantics).
// Branch-free: every push is an unconditional STS whose 32-bit offset selects
// between write cursor and a per-thread trash slot. np==4 statically.
__device__ __forceinline__ void clip_first(float a, float b, float c,
                                           float2 r0, float2 r1, float2 r2, float2 r3,
                                           float2* __restrict__ sp,
                                           int t, int& np, bool& frozen) {
    float2 r[5];
    r[0] = r0; r[1] = r1; r[2] = r2; r[3] = r3; r[4] = r0;
    float v[5];
#pragma unroll
    for (int j = 0; j < 5; j++)
        v[j] = a * r[j].x + b * r[j].y + c;

    const int TRASH = 9 * TPB + t;
    int wo = t;
    int nn = 0;
#pragma unroll
    for (int j = 0; j < 4; j++) {
        bool keep = (v[j] <= 0.0f);
        bool crs  = (v[j] * v[j + 1] < 0.0f);

        sp[keep ? wo : TRASH] = r[j];
        wo += keep ? TPB : 0;
        nn += keep ? 1 : 0;

        float tx = r[j + 1].x, ty = r[j + 1].y;
        float a2 = ty - r[j].y;
        float b2 = r[j].x - tx;
        float c2 = tx * r[j].y - ty * r[j].x;
        float wd = a * b2 - b * a2;
        float iw = __fdividef(1.0f, wd);
        float2 ip;
        ip.x = (b * c2 - c * b2) * iw;
        ip.y = (c * a2 - a * c2) * iw;
        sp[crs ? wo : TRASH] = ip;
        wo += crs ? TPB : 0;
        nn += crs ? 1 : 0;
    }

    bool ok = (nn > 0);
    float2 f0 = sp[t];               // new slot 0 (or intact seed if nn==0)
    sp[ok ? wo : TRASH] = f0;        // append wrap copy at slot nn
    np = ok ? nn : np;
    frozen = !ok;
}

// Subsequent passes: polygon lives in smem. Same branch-free push scheme.
// In-place safe: all INCAP+1 slots read before any write. Reads of slots
// >= np are predicate-discarded. Reference semantics preserved: keep =
// (val <= 0), crossing = strict sign change, frozen = empty result keeps
// the pre-clip polygon and stops clipping.
template <int INCAP>
__device__ __forceinline__ void clip_edge_smem(float a, float b, float c,
                                               float2* __restrict__ sp,
                                               int t, int& np, bool& frozen) {
    bool doPass = !frozen && (np > 2);

    float2 r[INCAP + 1];
    float v[INCAP + 1];
#pragma unroll
    for (int j = 0; j <= INCAP; j++) {
        r[j] = sp[j * TPB + t];
        v[j] = a * r[j].x + b * r[j].y + c;
    }

    const int TRASH = 9 * TPB + t;
    int wo = t;
    int nn = 0;
#pragma unroll
    for (int j = 0; j < INCAP; j++) {
        bool act  = doPass && (j < np);
        bool keep = act && (v[j] <= 0.0f);
        bool crs  = act && (v[j] * v[j + 1] < 0.0f);

        sp[keep ? wo : TRASH] = r[j];
        wo += keep ? TPB : 0;
        nn += keep ? 1 : 0;

        float tx = r[j + 1].x, ty = r[j + 1].y;
        float a2 = ty - r[j].y;
        float b2 = r[j].x - tx;
        float c2 = tx * r[j].y - ty * r[j].x;
        float wd = a * b2 - b * a2;
        float iw = __fdividef(1.0f, wd);
        float2 ip;
        ip.x = (b * c2 - c * b2) * iw;
        ip.y = (c * a2 - a * c2) * iw;
        sp[crs ? wo : TRASH] = ip;
        wo += crs ? TPB : 0;
        nn += crs ? 1 : 0;
    }

    bool ok = doPass && (nn > 0);
    float2 f0 = sp[t];
    sp[ok ? wo : TRASH] = f0;
    np = ok ? nn : np;
    frozen = frozen || (doPass && nn == 0);
}

__global__ void __launch_bounds__(TPB, 8)
giou_kernel(const float* __restrict__ pred,
            const float* __restrict__ tgt,
            float* __restrict__ out, int n) {
    __shared__ float2 s_xy[10 * TPB];  // clip polygon (+append, +trash slot)
    __shared__ float2 c_xy[8 * TPB];   // 8 corners (0-3 pred, 4-7 tgt)

    int t = threadIdx.x;
    int gi = blockIdx.x * TPB + t;
    bool act = (gi < n);
    int i = act ? gi : (n - 1);        // clamp: inactive threads duplicate
                                       // thread n-1's work (same values)

    const float2* pb = (const float2*)(pred + 6 * i);
    const float2* tb = (const float2*)(tgt + 6 * i);
    float2 p0 = __ldg(pb), p1 = __ldg(pb + 1), p2 = __ldg(pb + 2);
    float2 t0 = __ldg(tb), t1 = __ldg(tb + 1), t2 = __ldg(tb + 2);
    float area_sum = p1.x * p1.y + t1.x * t1.y;  // pa + ta

    // ---- corners: pred in registers (pass-1 input) AND seeded to smem
    //      (frozen-path fallback); both corner sets to c_xy for hull ----
    float2 c0, c1, c2, c3;
    {
        float rinv = rsqrtf(fmaf(p2.x, p2.x, p2.y * p2.y));
        float cth = p2.y * rinv, sth = p2.x * rinv;
        float hw = 0.5f * p1.x, hl = 0.5f * p1.y;
        c0 = make_float2(p0.x - hw * cth - hl * sth, p0.y - hw * sth + hl * cth);
        c1 = make_float2(p0.x - hw * cth + hl * sth, p0.y - hw * sth - hl * cth);
        c2 = make_float2(p0.x + hw * cth + hl * sth, p0.y + hw * sth - hl * cth);
        c3 = make_float2(p0.x + hw * cth - hl * sth, p0.y + hw * sth + hl * cth);
        c_xy[0 * TPB + t] = c0;
        c_xy[1 * TPB + t] = c1;
        c_xy[2 * TPB + t] = c2;
        c_xy[3 * TPB + t] = c3;
        // seed the clip polygon: REQUIRED for the frozen path (if pass 1
        // empties the polygon, the shoelace must see the intact pred quad)
        s_xy[0 * TPB + t] = c0;
        s_xy[1 * TPB + t] = c1;
        s_xy[2 * TPB + t] = c2;
        s_xy[3 * TPB + t] = c3;
        s_xy[4 * TPB + t] = c0;
    }
    {
        float rinv = rsqrtf(fmaf(t2.x, t2.x, t2.y * t2.y));
        float cth = t2.y * rinv, sth = t2.x * rinv;
        float hw = 0.5f * t1.x, hl = 0.5f * t1.y;
        c_xy[4 * TPB + t] = make_float2(t0.x - hw * cth - hl * sth, t0.y - hw * sth + hl * cth);
        c_xy[5 * TPB + t] = make_float2(t0.x - hw * cth + hl * sth, t0.y - hw * sth - hl * cth);
        c_xy[6 * TPB + t] = make_float2(t0.x + hw * cth + hl * sth, t0.y + hw * sth - hl * cth);
        c_xy[7 * TPB + t] = make_float2(t0.x + hw * cth - hl * sth, t0.y + hw * sth + hl * cth);
    }

    // ---- clip by the 4 target half-planes ----
    int np = 4;
    bool frozen = false;
    {
        // pass 1: input from registers (no smem readback on the fast path)
        float2 P = c_xy[4 * TPB + t];
        float2 Q = c_xy[5 * TPB + t];
        float a = Q.y - P.y, b = P.x - Q.x, c = Q.x * P.y - Q.y * P.x;
        clip_first(a, b, c, c0, c1, c2, c3, s_xy, t, np, frozen);
    }
#pragma unroll
    for (int e = 1; e < 4; e++) {
        const int e1 = (e + 1) & 3;
        float2 P = c_xy[(4 + e) * TPB + t];
        float2 Q = c_xy[(4 + e1) * TPB + t];
        float a = Q.y - P.y, b = P.x - Q.x, c = Q.x * P.y - Q.y * P.x;
        if (e == 1)      clip_edge_smem<5>(a, b, c, s_xy, t, np, frozen);
        else if (e == 2) clip_edge_smem<6>(a, b, c, s_xy, t, np, frozen);
        else             clip_edge_smem<7>(a, b, c, s_xy, t, np, frozen);
    }

    // ---- shoelace over final polygon (append makes next = j+1) ----
    float s2 = 0.0f;
    {
        float2 q[9];
#pragma unroll
        for (int k = 0; k < 9; k++) q[k] = s_xy[k * TPB + t];
#pragma unroll
        for (int j = 0; j < 8; j++) {
            bool a8 = (j < np);
            float tm = q[j].x * q[j + 1].y - q[j].y * q[j + 1].x;
            s2 += a8 ? tm : 0.0f;
        }
    }
    float inter = (np > 2) ? 0.5f * fabsf(s2) : 0.0f;

    float uni = area_sum - inter;
    float iou = inter * __fdividef(1.0f, uni + 1e-16f);
    out[i] = iou;   // inactive threads duplicate-write the same value

    // ---- convex hull area (reference all-pairs form) ----
    float2 P[8];
#pragma unroll
    for (int k = 0; k < 8; k++) P[k] = c_xy[k * TPB + t];

    float hs = 0.0f;
#pragma unroll
    for (int ii = 0; ii < 7; ii++) {   // pivot 7 owns no jj>ii pairs
        float dx[8], dy[8];
#pragma unroll
        for (int k = 0; k < 8; k++) {
            dx[k] = P[k].x - P[ii].x;
            dy[k] = P[k].y - P[ii].y;
        }
#pragma unroll
        for (int jj = ii + 1; jj < 8; jj++) {
            float ex = dx[jj], ey = dy[jj];
            float cr[6];
            int c6 = 0;
#pragma unroll
            for (int k = 0; k < 8; k++) {
                if (k == ii || k == jj) continue;  // cross == 0 there
                cr[c6++] = ex * dy[k] - ey * dx[k];
            }
            float mn = fminf(fminf(fminf(cr[0], cr[1]), fminf(cr[2], cr[3])),
                             fminf(cr[4], cr[5]));
            float mx = fmaxf(fmaxf(fmaxf(cr[0], cr[1]), fmaxf(cr[2], cr[3])),
                             fmaxf(cr[4], cr[5]));
            float len2 = ex * ex + ey * ey;
            bool okL = (len2 > 1e-12f) && (mn >= -1e-6f);  // ii -> jj
            bool okR = (len2 > 1e-12f) && (mx <= 1e-6f);   // jj -> ii
            float cij = P[ii].x * ey - P[ii].y * ex;  // == xi*yj - yi*xj
            hs += okL ? cij : 0.0f;
            hs += okR ? -cij : 0.0f;
        }
    }
    float hull = 0.5f * fabsf(hs);

    float giou = 1.0f - (iou - (hull - uni) * __fdividef(1.0f, hull + 1e-16f));
    giou = act ? giou : 0.0f;

    // ---- deterministic in-kernel reduction ----
#pragma unroll
    for (int off = 16; off > 0; off >>= 1)
        giou += __shfl_down_sync(0xffffffffu, giou, off);

    __shared__ float wsum[TPB / 32];
    __shared__ bool isLast;
    if ((t & 31) == 0) wsum[t >> 5] = giou;
    __syncthreads();

    if (t == 0) {
        float bs = 0.0f;
#pragma unroll
        for (int w = 0; w < TPB / 32; w++) bs += wsum[w];
        g_partials[blockIdx.x] = bs;
        __threadfence();
        unsigned c = atomicAdd(&g_count, 1u);
        isLast = (c == gridDim.x - 1);
    }
    __syncthreads();

    if (isLast) {
        __threadfence();
        float v = 0.0f;
        for (int j = t; j < (int)gridDim.x; j += TPB)
            v += ((volatile float*)g_partials)[j];
#pragma unroll
        for (int off = 16; off > 0; off >>= 1)
            v += __shfl_down_sync(0xffffffffu, v, off);
        if ((t & 31) == 0) wsum[t >> 5] = v;
        __syncthreads();
        if (t == 0) {
            float tot = 0.0f;
#pragma unroll
            for (int w = 0; w < TPB / 32; w++) tot += wsum[w];
            out[n] = tot;
            g_count = 0;  // reset for next graph replay
        }
    }
}

extern "C" void kernel_launch(void* const* d_in, const int* in_sizes, int n_in,
                              void* d_out, int out_size) {
    const float* pred = (const float*)d_in[0];
    const float* tgt  = (const float*)d_in[1];
    float* out = (float*)d_out;
    int n = in_sizes[0] / 6;
    int nblocks = (n + TPB - 1) / TPB;
    giou_kernel<<<nblocks, TPB>>>(pred, tgt, out, n);
}

// round 15
// speedup vs baseline: 1.1398x; 1.1165x over previous
#include <cuda_runtime.h>
#include <math.h>

#define TPB 128
#define NPART 2048

__device__ float g_partials[NPART];
__device__ unsigned int g_count;

// One Sutherland-Hodgman clip pass -- FULLY BRANCH-FREE.
// Polygon lives in a thread-private smem column of float2 ([slot][tid],
// stride TPB -> conflict-free 64-bit accesses). Slot 9 is a per-thread
// trash slot: every push is an unconditional STS whose 32-bit offset is
// selected between the write cursor and trash, so no BSSY/BSYNC divergence.
// Wraparound handled by an appended copy of vertex 0 at slot np.
// In-place safe: all INCAP+1 slots are read before any write.
// Reads of slots >= np are predicate-discarded; garbage there is harmless.
// Reference semantics: keep = (val <= 0), crossing = strict sign change,
// frozen = empty result -> keep pre-clip polygon, stop clipping.
// Intersection uses the parametric form I = p + (v_p/(v_p-v_q))*(q-p):
// algebraically identical to the reference's determinant form (same lines),
// differs only in rounding.
template <int INCAP>
__device__ __forceinline__ void clip_edge_smem(float a, float b, float c,
                                               float2* __restrict__ sp,
                                               int t, int& np, bool& frozen) {
    bool doPass = !frozen && (np > 2);

    float2 r[INCAP + 1];
    float v[INCAP + 1];
#pragma unroll
    for (int j = 0; j <= INCAP; j++) {
        r[j] = sp[j * TPB + t];
        v[j] = a * r[j].x + b * r[j].y + c;
    }

    const int TRASH = 9 * TPB + t;   // per-thread trash slot offset
    int wo = t;                      // write cursor offset (32-bit)
    int nn = 0;
#pragma unroll
    for (int j = 0; j < INCAP; j++) {
        bool act  = doPass && (j < np);
        bool keep = act && (v[j] <= 0.0f);
        bool crs  = act && (v[j] * v[j + 1] < 0.0f);

        // keep push (unconditional store, selected 32-bit offset)
        sp[keep ? wo : TRASH] = r[j];
        wo += keep ? TPB : 0;
        nn += keep ? 1 : 0;

        // intersection, parametric form (computed unconditionally;
        // trash absorbs garbage; crossing guarantees denom != 0)
        float w = __fdividef(v[j], v[j] - v[j + 1]);
        float2 ip;
        ip.x = fmaf(w, r[j + 1].x - r[j].x, r[j].x);
        ip.y = fmaf(w, r[j + 1].y - r[j].y, r[j].y);
        sp[crs ? wo : TRASH] = ip;
        wo += crs ? TPB : 0;
        nn += crs ? 1 : 0;
    }

    // append new vertex 0 at slot nn (branch-free), update state by selects
    bool ok = doPass && (nn > 0);
    float2 f0 = sp[t];               // new slot 0 (if any push happened)
    sp[ok ? wo : TRASH] = f0;        // wo == nn*TPB + t
    np = ok ? nn : np;               // geometric bound: nn <= INCAP+1 <= 8
    frozen = frozen || (doPass && nn == 0);
}

__global__ void __launch_bounds__(TPB, 8)
giou_kernel(const float* __restrict__ pred,
            const float* __restrict__ tgt,
            float* __restrict__ out, int n) {
    __shared__ float2 s_xy[10 * TPB];  // clip polygon (+append, +trash slot)
    __shared__ float2 c_xy[8 * TPB];   // 8 corners (0-3 pred, 4-7 tgt)

    int t = threadIdx.x;
    int i = blockIdx.x * TPB + t;
    float giou = 0.0f;

    if (i < n) {
        const float2* pb = (const float2*)(pred + 6 * i);
        const float2* tb = (const float2*)(tgt + 6 * i);
        float2 p0 = __ldg(pb), p1 = __ldg(pb + 1), p2 = __ldg(pb + 2);
        float2 t0 = __ldg(tb), t1 = __ldg(tb + 1), t2 = __ldg(tb + 2);
        float area_sum = p1.x * p1.y + t1.x * t1.y;  // pa + ta

        // ---- corners into smem (float2); pred corners seed polygon + append ----
        {
            float rinv = rsqrtf(fmaf(p2.x, p2.x, p2.y * p2.y));
            float cth = p2.y * rinv, sth = p2.x * rinv;
            float hw = 0.5f * p1.x, hl = 0.5f * p1.y;
            float2 c0 = make_float2(p0.x - hw * cth - hl * sth, p0.y - hw * sth + hl * cth);
            float2 c1 = make_float2(p0.x - hw * cth + hl * sth, p0.y - hw * sth - hl * cth);
            float2 c2 = make_float2(p0.x + hw * cth + hl * sth, p0.y + hw * sth - hl * cth);
            float2 c3 = make_float2(p0.x + hw * cth - hl * sth, p0.y + hw * sth + hl * cth);
            c_xy[0 * TPB + t] = c0;  s_xy[0 * TPB + t] = c0;
            c_xy[1 * TPB + t] = c1;  s_xy[1 * TPB + t] = c1;
            c_xy[2 * TPB + t] = c2;  s_xy[2 * TPB + t] = c2;
            c_xy[3 * TPB + t] = c3;  s_xy[3 * TPB + t] = c3;
            s_xy[4 * TPB + t] = c0;  // append: wraparound copy of vertex 0
        }
        {
            float rinv = rsqrtf(fmaf(t2.x, t2.x, t2.y * t2.y));
            float cth = t2.y * rinv, sth = t2.x * rinv;
            float hw = 0.5f * t1.x, hl = 0.5f * t1.y;
            c_xy[4 * TPB + t] = make_float2(t0.x - hw * cth - hl * sth, t0.y - hw * sth + hl * cth);
            c_xy[5 * TPB + t] = make_float2(t0.x - hw * cth + hl * sth, t0.y - hw * sth - hl * cth);
            c_xy[6 * TPB + t] = make_float2(t0.x + hw * cth + hl * sth, t0.y + hw * sth - hl * cth);
            c_xy[7 * TPB + t] = make_float2(t0.x + hw * cth - hl * sth, t0.y + hw * sth + hl * cth);
        }

        // ---- clip by the 4 target half-planes (planes built JIT from smem) ----
        int np = 4;
        bool frozen = false;
#pragma unroll
        for (int e = 0; e < 4; e++) {
            const int e1 = (e + 1) & 3;
            float2 P = c_xy[(4 + e) * TPB + t];
            float2 Q = c_xy[(4 + e1) * TPB + t];
            float a = Q.y - P.y;
            float b = P.x - Q.x;
            float c = Q.x * P.y - Q.y * P.x;
            if (e == 0)      clip_edge_smem<4>(a, b, c, s_xy, t, np, frozen);
            else if (e == 1) clip_edge_smem<5>(a, b, c, s_xy, t, np, frozen);
            else if (e == 2) clip_edge_smem<6>(a, b, c, s_xy, t, np, frozen);
            else             clip_edge_smem<7>(a, b, c, s_xy, t, np, frozen);
        }

        // ---- shoelace over final polygon (append makes next = j+1) ----
        float s2 = 0.0f;
        {
            float2 q[9];
#pragma unroll
            for (int k = 0; k < 9; k++) q[k] = s_xy[k * TPB + t];
#pragma unroll
            for (int j = 0; j < 8; j++) {
                bool act = (j < np);
                float tm = q[j].x * q[j + 1].y - q[j].y * q[j + 1].x;
                s2 += act ? tm : 0.0f;
            }
        }
        float inter = (np > 2) ? 0.5f * fabsf(s2) : 0.0f;

        float uni = area_sum - inter;
        float iou = inter * __fdividef(1.0f, uni + 1e-16f);
        out[i] = iou;

        // ---- convex hull area (reference all-pairs form) ----
        // Corners in registers (clip pressure over). Antisymmetry: each
        // unordered pair once, both directed validities via min/max trees.
        float2 P[8];
#pragma unroll
        for (int k = 0; k < 8; k++) P[k] = c_xy[k * TPB + t];

        float hs = 0.0f;
#pragma unroll
        for (int ii = 0; ii < 7; ii++) {   // pivot 7 owns no jj>ii pairs
            float dx[8], dy[8];
#pragma unroll
            for (int k = 0; k < 8; k++) {
                dx[k] = P[k].x - P[ii].x;
                dy[k] = P[k].y - P[ii].y;
            }
#pragma unroll
            for (int jj = ii + 1; jj < 8; jj++) {
                float ex = dx[jj], ey = dy[jj];
                float cr[6];
                int c6 = 0;
#pragma unroll
                for (int k = 0; k < 8; k++) {
                    if (k == ii || k == jj) continue;  // cross == 0 there
                    cr[c6++] = ex * dy[k] - ey * dx[k];
                }
                float mn = fminf(fminf(fminf(cr[0], cr[1]), fminf(cr[2], cr[3])),
                                 fminf(cr[4], cr[5]));
                float mx = fmaxf(fmaxf(fmaxf(cr[0], cr[1]), fmaxf(cr[2], cr[3])),
                                 fmaxf(cr[4], cr[5]));
                float len2 = ex * ex + ey * ey;
                bool okL = (len2 > 1e-12f) && (mn >= -1e-6f);  // ii -> jj
                bool okR = (len2 > 1e-12f) && (mx <= 1e-6f);   // jj -> ii
                float cij = P[ii].x * ey - P[ii].y * ex;  // == xi*yj - yi*xj
                hs += okL ? cij : 0.0f;
                hs += okR ? -cij : 0.0f;
            }
        }
        float hull = 0.5f * fabsf(hs);

        giou = 1.0f - (iou - (hull - uni) * __fdividef(1.0f, hull + 1e-16f));
    }

    // ---- deterministic in-kernel reduction ----
#pragma unroll
    for (int off = 16; off > 0; off >>= 1)
        giou += __shfl_down_sync(0xffffffffu, giou, off);

    __shared__ float wsum[TPB / 32];
    __shared__ bool isLast;
    if ((t & 31) == 0) wsum[t >> 5] = giou;
    __syncthreads();

    if (t == 0) {
        float bs = 0.0f;
#pragma unroll
        for (int w = 0; w < TPB / 32; w++) bs += wsum[w];
        g_partials[blockIdx.x] = bs;
        __threadfence();
        unsigned c = atomicAdd(&g_count, 1u);
        isLast = (c == gridDim.x - 1);
    }
    __syncthreads();

    if (isLast) {
        __threadfence();
        float v = 0.0f;
        for (int j = t; j < (int)gridDim.x; j += TPB)
            v += ((volatile float*)g_partials)[j];
#pragma unroll
        for (int off = 16; off > 0; off >>= 1)
            v += __shfl_down_sync(0xffffffffu, v, off);
        if ((t & 31) == 0) wsum[t >> 5] = v;
        __syncthreads();
        if (t == 0) {
            float tot = 0.0f;
#pragma unroll
            for (int w = 0; w < TPB / 32; w++) tot += wsum[w];
            out[n] = tot;
            g_count = 0;  // reset for next graph replay
        }
    }
}

extern "C" void kernel_launch(void* const* d_in, const int* in_sizes, int n_in,
                              void* d_out, int out_size) {
    const float* pred = (const float*)d_in[0];
    const float* tgt  = (const float*)d_in[1];
    float* out = (float*)d_out;
    int n = in_sizes[0] / 6;
    int nblocks = (n + TPB - 1) / TPB;
    giou_kernel<<<nblocks, TPB>>>(pred, tgt, out, n);
}